// round 7
// baseline (speedup 1.0000x reference)
#include <cuda_runtime.h>
#include <cuda_bf16.h>
#include <math.h>

// Problem constants
#define BB   16
#define LQ   1024
#define DD   256
#define HH   8
#define LL   4
#define PP   4
#define DFF  1024
#define LV   5440
#define DH   32
#define NTOK (BB*LQ)        // 16384
#define NV   (BB*LV)        // 87040

typedef unsigned long long ull;

__device__ __forceinline__ unsigned f2tf32(float f) {
    unsigned r;
    asm("cvt.rna.tf32.f32 %0, %1;" : "=r"(r) : "f"(f));
    return r;
}
__device__ __forceinline__ void mma_tf32(float* c, const unsigned* a, unsigned b0, unsigned b1) {
    asm volatile(
        "mma.sync.aligned.m16n8k8.row.col.f32.tf32.tf32.f32 "
        "{%0,%1,%2,%3}, {%4,%5,%6,%7}, {%8,%9}, {%0,%1,%2,%3};"
        : "+f"(c[0]), "+f"(c[1]), "+f"(c[2]), "+f"(c[3])
        : "r"(a[0]), "r"(a[1]), "r"(a[2]), "r"(a[3]), "r"(b0), "r"(b1));
}

// ---------------- scratch (device globals; no allocs allowed) ----------------
__device__ float g_qk  [(size_t)NTOK*512];
__device__ float g_v   [(size_t)NTOK*256];
__device__ float g_att [(size_t)NTOK*256];
__device__ float g_att2[(size_t)NTOK*256];
__device__ float g_t1  [(size_t)NTOK*256];
__device__ float g_value[(size_t)NV*256];
__device__ float g_off [(size_t)NTOK*256];
__device__ float g_attw[(size_t)NTOK*128];
__device__ float g_samp[(size_t)NTOK*256];
__device__ float g_ms  [(size_t)NTOK*256];
__device__ float g_t2  [(size_t)NTOK*256];
__device__ float g_ffn1[(size_t)NTOK*1024];
__device__ float g_ffn2[(size_t)NTOK*256];

// ---------------- tensor-core GEMM (tf32 mma.sync) ---------------------------
// C[N,M] = (A0 (+A1))[N,K] @ W[M,K]^T + bias  (optional relu)
// 128x128 tile, KC=32, 128 threads = 4 warps (2 row x 2 col), 64x64 per warp
// (4 mt x 8 nt m16n8k8 MMAs). smem rows pair-permuted: slot 2t holds k=t,
// slot 2t+1 holds k=t+4 within each 8-group. Fill uses STS.128 (conflict-free
// at stride 36: lanes span banks 4t..4t+3); fragment loads are LDS.64 (2-way
// = minimum phases).
#define GSTRIDE 36
__global__ void __launch_bounds__(128, 2) gemm_tc(
    const float* __restrict__ A0, const float* __restrict__ A1,
    const float* __restrict__ W,  const float* __restrict__ bias,
    float* __restrict__ C, int N, int K, int M, int relu)
{
    __shared__ unsigned As[128][GSTRIDE];
    __shared__ unsigned Bs[128][GSTRIDE];

    const int tid  = threadIdx.x;
    const int lane = tid & 31;
    const int wid  = tid >> 5;
    const int wr   = wid & 1;          // row half (0/1) -> rows 64*wr
    const int wc   = wid >> 1;         // col half (0/1) -> cols 64*wc
    const int g    = lane >> 2;
    const int tig  = lane & 3;
    const int r0 = blockIdx.y * 128;
    const int c0 = blockIdx.x * 128;

    float acc[4][8][4];
    #pragma unroll
    for (int mt = 0; mt < 4; mt++)
        #pragma unroll
        for (int nt = 0; nt < 8; nt++)
            #pragma unroll
            for (int c = 0; c < 4; c++) acc[mt][nt][c] = 0.f;

    // fill: each thread owns one A row and one B row (128 rows each)
    const float* ApF  = A0 + (size_t)(r0 + tid) * K;
    const float* A1pF = A1 ? (A1 + (size_t)(r0 + tid) * K) : nullptr;
    const float* WpF  = W  + (size_t)(c0 + tid) * K;

    for (int kt = 0; kt < K; kt += 32) {
        __syncthreads();
        #pragma unroll
        for (int grp = 0; grp < 4; grp++) {
            // A row
            {
                float4 lo = *(const float4*)(ApF + kt + grp * 8);
                float4 hi = *(const float4*)(ApF + kt + grp * 8 + 4);
                if (A1pF) {
                    float4 l1 = *(const float4*)(A1pF + kt + grp * 8);
                    float4 h1 = *(const float4*)(A1pF + kt + grp * 8 + 4);
                    lo.x += l1.x; lo.y += l1.y; lo.z += l1.z; lo.w += l1.w;
                    hi.x += h1.x; hi.y += h1.y; hi.z += h1.z; hi.w += h1.w;
                }
                uint4 s0 = make_uint4(f2tf32(lo.x), f2tf32(hi.x), f2tf32(lo.y), f2tf32(hi.y));
                uint4 s1 = make_uint4(f2tf32(lo.z), f2tf32(hi.z), f2tf32(lo.w), f2tf32(hi.w));
                *(uint4*)&As[tid][grp*8+0] = s0;
                *(uint4*)&As[tid][grp*8+4] = s1;
            }
            // B row
            {
                float4 lo = *(const float4*)(WpF + kt + grp * 8);
                float4 hi = *(const float4*)(WpF + kt + grp * 8 + 4);
                uint4 s0 = make_uint4(f2tf32(lo.x), f2tf32(hi.x), f2tf32(lo.y), f2tf32(hi.y));
                uint4 s1 = make_uint4(f2tf32(lo.z), f2tf32(hi.z), f2tf32(lo.w), f2tf32(hi.w));
                *(uint4*)&Bs[tid][grp*8+0] = s0;
                *(uint4*)&Bs[tid][grp*8+4] = s1;
            }
        }
        __syncthreads();

        #pragma unroll
        for (int k8 = 0; k8 < 4; k8++) {
            unsigned af[4][4];
            #pragma unroll
            for (int mt = 0; mt < 4; mt++) {
                const int rowa = wr * 64 + mt * 16 + g;
                uint2 p0 = *(const uint2*)&As[rowa    ][k8 * 8 + 2 * tig];
                uint2 p1 = *(const uint2*)&As[rowa + 8][k8 * 8 + 2 * tig];
                af[mt][0] = p0.x; af[mt][1] = p1.x; af[mt][2] = p0.y; af[mt][3] = p1.y;
            }
            #pragma unroll
            for (int nt = 0; nt < 8; nt++) {
                const int coln = wc * 64 + nt * 8 + g;
                uint2 p = *(const uint2*)&Bs[coln][k8 * 8 + 2 * tig];
                #pragma unroll
                for (int mt = 0; mt < 4; mt++)
                    mma_tf32(acc[mt][nt], af[mt], p.x, p.y);
            }
        }
    }

    #pragma unroll
    for (int nt = 0; nt < 8; nt++) {
        const int col = c0 + wc * 64 + nt * 8 + 2 * tig;
        float2 bi = *(const float2*)(bias + col);
        #pragma unroll
        for (int mt = 0; mt < 4; mt++) {
            const int row = r0 + wr * 64 + mt * 16 + g;
            float2 lo, hi;
            lo.x = acc[mt][nt][0] + bi.x; lo.y = acc[mt][nt][1] + bi.y;
            hi.x = acc[mt][nt][2] + bi.x; hi.y = acc[mt][nt][3] + bi.y;
            if (relu) {
                lo.x = fmaxf(lo.x, 0.f); lo.y = fmaxf(lo.y, 0.f);
                hi.x = fmaxf(hi.x, 0.f); hi.y = fmaxf(hi.y, 0.f);
            }
            *(float2*)(C + (size_t)row * M + col)       = lo;
            *(float2*)(C + (size_t)(row + 8) * M + col) = hi;
        }
    }
}

// ---------------- tensor-core flash attention (tf32) -------------------------
// grid (LQ/64, B*H), 128 threads = 4 warps, 16 queries per warp.
// QK: [NTOK,512] (q | k), V: [NTOK,256] head-interleaved.
#define KSTR 36
#define VSTR 66
__global__ void __launch_bounds__(128) attn_tc(
    const float* __restrict__ QK, const float* __restrict__ V, float* __restrict__ O)
{
    __shared__ unsigned Ks[64][KSTR];
    __shared__ unsigned Vs[32][VSTR];

    const int bh = blockIdx.y;
    const int b = bh >> 3, h = bh & 7;
    const int q0 = blockIdx.x * 64;
    const int tid = threadIdx.x;
    const int lane = tid & 31;
    const int wid = tid >> 5;
    const int g = lane >> 2;
    const int tig = lane & 3;

    // Q fragments (scaled by 1/sqrt(DH), tf32)
    const float scale = 0.17677669529663687f;
    unsigned qf[4][4];
    {
        const size_t qb = ((size_t)b * LQ + q0 + wid * 16) * 512 + h * 32;
        #pragma unroll
        for (int s = 0; s < 4; s++) {
            qf[s][0] = f2tf32(QK[qb + (size_t)g      * 512 + s*8 + tig    ] * scale);
            qf[s][1] = f2tf32(QK[qb + (size_t)(g + 8)* 512 + s*8 + tig    ] * scale);
            qf[s][2] = f2tf32(QK[qb + (size_t)g      * 512 + s*8 + tig + 4] * scale);
            qf[s][3] = f2tf32(QK[qb + (size_t)(g + 8)* 512 + s*8 + tig + 4] * scale);
        }
    }

    float oa[4][4];
    #pragma unroll
    for (int i = 0; i < 4; i++)
        #pragma unroll
        for (int j = 0; j < 4; j++) oa[i][j] = 0.f;
    float m0 = -1e30f, m1 = -1e30f, l0 = 0.f, l1 = 0.f;

    const size_t kbase = ((size_t)b * LQ) * 512 + 256 + h * 32;
    const size_t vbase = ((size_t)b * LQ) * 256 + h * 32;

    for (int kt = 0; kt < LQ; kt += 64) {
        __syncthreads();
        // fill K tile [64 keys x 32 k], pair-permuted
        {
            const int key = tid >> 1, kh = (tid & 1) * 16;
            const float* kp = QK + kbase + (size_t)(kt + key) * 512 + kh;
            #pragma unroll
            for (int g2 = 0; g2 < 2; g2++) {
                float4 lo = *(const float4*)(kp + g2 * 8);
                float4 hi = *(const float4*)(kp + g2 * 8 + 4);
                const int d = kh + g2 * 8;
                *(uint2*)&Ks[key][d+0] = make_uint2(f2tf32(lo.x), f2tf32(hi.x));
                *(uint2*)&Ks[key][d+2] = make_uint2(f2tf32(lo.y), f2tf32(hi.y));
                *(uint2*)&Ks[key][d+4] = make_uint2(f2tf32(lo.z), f2tf32(hi.z));
                *(uint2*)&Ks[key][d+6] = make_uint2(f2tf32(lo.w), f2tf32(hi.w));
            }
        }
        // fill V tile transposed: Vs[d][perm(key)]
        {
            const int key = tid >> 1, dh = (tid & 1) * 16;
            const int j = key & 7;
            const int pos = (key >> 3) * 8 + 2 * (j & 3) + (j >> 2);
            const float* vp = V + vbase + (size_t)(kt + key) * 256 + dh;
            #pragma unroll
            for (int i = 0; i < 4; i++) {
                float4 v = *(const float4*)(vp + i * 4);
                Vs[dh + i*4 + 0][pos] = f2tf32(v.x);
                Vs[dh + i*4 + 1][pos] = f2tf32(v.y);
                Vs[dh + i*4 + 2][pos] = f2tf32(v.z);
                Vs[dh + i*4 + 3][pos] = f2tf32(v.w);
            }
        }
        __syncthreads();

        // S = Q K^T : 8 n-tiles x 4 k-steps
        float sa[8][4];
        #pragma unroll
        for (int nt = 0; nt < 8; nt++)
            #pragma unroll
            for (int c = 0; c < 4; c++) sa[nt][c] = 0.f;
        #pragma unroll
        for (int s = 0; s < 4; s++)
            #pragma unroll
            for (int nt = 0; nt < 8; nt++) {
                uint2 p = *(const uint2*)&Ks[nt*8 + g][s*8 + 2*tig];
                mma_tf32(sa[nt], qf[s], p.x, p.y);
            }

        // online softmax (thread rows: r0 = g, r1 = g+8 of warp tile)
        float cm0 = -1e30f, cm1 = -1e30f;
        #pragma unroll
        for (int nt = 0; nt < 8; nt++) {
            cm0 = fmaxf(cm0, fmaxf(sa[nt][0], sa[nt][1]));
            cm1 = fmaxf(cm1, fmaxf(sa[nt][2], sa[nt][3]));
        }
        cm0 = fmaxf(cm0, __shfl_xor_sync(0xffffffffu, cm0, 1));
        cm0 = fmaxf(cm0, __shfl_xor_sync(0xffffffffu, cm0, 2));
        cm1 = fmaxf(cm1, __shfl_xor_sync(0xffffffffu, cm1, 1));
        cm1 = fmaxf(cm1, __shfl_xor_sync(0xffffffffu, cm1, 2));
        const float nm0 = fmaxf(m0, cm0), nm1 = fmaxf(m1, cm1);
        const float r0s = __expf(m0 - nm0), r1s = __expf(m1 - nm1);
        l0 *= r0s; l1 *= r1s;
        #pragma unroll
        for (int d = 0; d < 4; d++) {
            oa[d][0] *= r0s; oa[d][1] *= r0s;
            oa[d][2] *= r1s; oa[d][3] *= r1s;
        }
        float ps0 = 0.f, ps1 = 0.f;
        #pragma unroll
        for (int nt = 0; nt < 8; nt++) {
            sa[nt][0] = __expf(sa[nt][0] - nm0); ps0 += sa[nt][0];
            sa[nt][1] = __expf(sa[nt][1] - nm0); ps0 += sa[nt][1];
            sa[nt][2] = __expf(sa[nt][2] - nm1); ps1 += sa[nt][2];
            sa[nt][3] = __expf(sa[nt][3] - nm1); ps1 += sa[nt][3];
        }
        ps0 += __shfl_xor_sync(0xffffffffu, ps0, 1);
        ps0 += __shfl_xor_sync(0xffffffffu, ps0, 2);
        ps1 += __shfl_xor_sync(0xffffffffu, ps1, 1);
        ps1 += __shfl_xor_sync(0xffffffffu, ps1, 2);
        l0 += ps0; l1 += ps1;
        m0 = nm0; m1 = nm1;

        // P (C-layout) -> A-layout via shfl, then O += P V
        const int src1 = (lane & ~3) | (tig >> 1);
        const int src2 = src1 + 2;
        #pragma unroll
        for (int nt = 0; nt < 8; nt++) {
            float v0a = __shfl_sync(0xffffffffu, sa[nt][0], src1);
            float v1a = __shfl_sync(0xffffffffu, sa[nt][1], src1);
            float v0b = __shfl_sync(0xffffffffu, sa[nt][0], src2);
            float v1b = __shfl_sync(0xffffffffu, sa[nt][1], src2);
            float w0a = __shfl_sync(0xffffffffu, sa[nt][2], src1);
            float w1a = __shfl_sync(0xffffffffu, sa[nt][3], src1);
            float w0b = __shfl_sync(0xffffffffu, sa[nt][2], src2);
            float w1b = __shfl_sync(0xffffffffu, sa[nt][3], src2);
            unsigned pa[4];
            pa[0] = f2tf32((tig & 1) ? v1a : v0a);
            pa[1] = f2tf32((tig & 1) ? w1a : w0a);
            pa[2] = f2tf32((tig & 1) ? v1b : v0b);
            pa[3] = f2tf32((tig & 1) ? w1b : w0b);
            #pragma unroll
            for (int d = 0; d < 4; d++) {
                uint2 bv = *(const uint2*)&Vs[d*8 + g][nt*8 + 2*tig];
                mma_tf32(oa[d], pa, bv.x, bv.y);
            }
        }
    }

    const float inv0 = 1.f / l0, inv1 = 1.f / l1;
    const size_t orow = ((size_t)b * LQ + q0 + wid * 16 + g) * 256 + h * 32;
    #pragma unroll
    for (int d = 0; d < 4; d++) {
        float2 lo, hi;
        lo.x = oa[d][0] * inv0; lo.y = oa[d][1] * inv0;
        hi.x = oa[d][2] * inv1; hi.y = oa[d][3] * inv1;
        *(float2*)(O + orow + d*8 + 2*tig)            = lo;
        *(float2*)(O + orow + 8*256 + d*8 + 2*tig)    = hi;
    }
}

// ---------------- residual + layernorm: Y = LN(A + Bres) ---------------------
__global__ void __launch_bounds__(256) ln_kernel(
    const float* __restrict__ A, const float* __restrict__ Bres,
    const float* __restrict__ g, const float* __restrict__ beta,
    float* __restrict__ Y)
{
    const int warp = threadIdx.x >> 5, lane = threadIdx.x & 31;
    const size_t row = (size_t)blockIdx.x * 8 + warp;
    const float* a = A    + row * 256;
    const float* b = Bres + row * 256;
    float v[8];
    #pragma unroll
    for (int i = 0; i < 2; i++) {
        float4 x = *(const float4*)(a + i*128 + lane*4);
        float4 y = *(const float4*)(b + i*128 + lane*4);
        v[i*4+0] = x.x + y.x; v[i*4+1] = x.y + y.y;
        v[i*4+2] = x.z + y.z; v[i*4+3] = x.w + y.w;
    }
    float sum = 0.f, sq = 0.f;
    #pragma unroll
    for (int i = 0; i < 8; i++) { sum += v[i]; sq = fmaf(v[i], v[i], sq); }
    #pragma unroll
    for (int off = 16; off > 0; off >>= 1) {
        sum += __shfl_xor_sync(0xffffffffu, sum, off);
        sq  += __shfl_xor_sync(0xffffffffu, sq,  off);
    }
    const float mean = sum * (1.f/256.f);
    const float var  = sq * (1.f/256.f) - mean * mean;
    const float inv  = rsqrtf(var + 1e-5f);
    #pragma unroll
    for (int i = 0; i < 2; i++) {
        const int col = i*128 + lane*4;
        float4 gg = *(const float4*)(g + col);
        float4 bb = *(const float4*)(beta + col);
        float4 out;
        out.x = (v[i*4+0]-mean)*inv*gg.x + bb.x;
        out.y = (v[i*4+1]-mean)*inv*gg.y + bb.y;
        out.z = (v[i*4+2]-mean)*inv*gg.z + bb.z;
        out.w = (v[i*4+3]-mean)*inv*gg.w + bb.w;
        *(float4*)(Y + row*256 + col) = out;
    }
}

// ---------------- softmax over 16 contiguous values per (token,h) ------------
__global__ void __launch_bounds__(256) softmax16_kernel(float* __restrict__ W)
{
    const int tid = blockIdx.x * 256 + threadIdx.x;
    if (tid >= NTOK * HH) return;
    float* p = W + (size_t)tid * 16;
    float v[16];
    #pragma unroll
    for (int i = 0; i < 4; i++) {
        float4 t = *(const float4*)(p + i*4);
        v[i*4+0]=t.x; v[i*4+1]=t.y; v[i*4+2]=t.z; v[i*4+3]=t.w;
    }
    float mx = v[0];
    #pragma unroll
    for (int i = 1; i < 16; i++) mx = fmaxf(mx, v[i]);
    float s = 0.f;
    #pragma unroll
    for (int i = 0; i < 16; i++) { v[i] = __expf(v[i]-mx); s += v[i]; }
    const float inv = 1.f / s;
    #pragma unroll
    for (int i = 0; i < 4; i++) {
        float4 t;
        t.x=v[i*4+0]*inv; t.y=v[i*4+1]*inv; t.z=v[i*4+2]*inv; t.w=v[i*4+3]*inv;
        *(float4*)(p + i*4) = t;
    }
}

// ---------------- deformable bilinear sampling -------------------------------
__device__ __forceinline__ float fetch_v(const float* __restrict__ value, size_t vb,
                                         int start, int WL2, int HL2, int xi, int yi)
{
    const bool ok = ((unsigned)xi < (unsigned)WL2) & ((unsigned)yi < (unsigned)HL2);
    const int xc = min(max(xi, 0), WL2 - 1);
    const int yc = min(max(yi, 0), HL2 - 1);
    const float val = value[vb + (size_t)(start + yc * WL2 + xc) * 256];
    return ok ? val : 0.f;
}

__global__ void __launch_bounds__(256) sample_kernel(
    const float* __restrict__ ref, const float* __restrict__ off,
    const float* __restrict__ attw, const float* __restrict__ value,
    float* __restrict__ out)
{
    const int wg   = blockIdx.x * 8 + (threadIdx.x >> 5);
    const int lane = threadIdx.x & 31;
    const int h  = wg & 7;
    const int tq = wg >> 3;            // b*LQ + q
    const int b  = tq >> 10;

    const float* refp = ref  + (size_t)tq * (LL*2);
    const float* offp = off  + (size_t)tq * 256 + h * 32;
    const float* awp  = attw + (size_t)tq * 128 + h * 16;
    const size_t vb   = ((size_t)b * LV) * 256 + h * 32 + lane;

    const int wls[4]    = {64, 32, 16, 8};
    const int hls[4]    = {64, 32, 16, 8};
    const int starts[4] = {0, 4096, 5120, 5376};

    float acc = 0.f;
    #pragma unroll
    for (int l = 0; l < 4; l++) {
        const int WL2 = wls[l], HL2 = hls[l], st = starts[l];
        const float rx = refp[l*2], ry = refp[l*2+1];
        #pragma unroll
        for (int p = 0; p < 4; p++) {
            const float ox = offp[(l*4+p)*2];
            const float oy = offp[(l*4+p)*2+1];
            const float aw = awp[l*4+p];
            const float x = fmaf(rx, (float)WL2, ox) - 0.5f;
            const float y = fmaf(ry, (float)HL2, oy) - 0.5f;
            const float xf = floorf(x), yf = floorf(y);
            const float lx = x - xf, ly = y - yf;
            const int x0 = (int)xf, y0 = (int)yf;
            const float v00 = fetch_v(value, vb, st, WL2, HL2, x0,   y0);
            const float v01 = fetch_v(value, vb, st, WL2, HL2, x0+1, y0);
            const float v10 = fetch_v(value, vb, st, WL2, HL2, x0,   y0+1);
            const float v11 = fetch_v(value, vb, st, WL2, HL2, x0+1, y0+1);
            const float top = v00 + lx * (v01 - v00);
            const float bot = v10 + lx * (v11 - v10);
            acc = fmaf(aw, top + ly * (bot - top), acc);
        }
    }
    out[(size_t)tq * 256 + h * 32 + lane] = acc;
}

// ---------------- host orchestration -----------------------------------------
extern "C" void kernel_launch(void* const* d_in, const int* in_sizes, int n_in,
                              void* d_out, int out_size)
{
    const float* tgt     = (const float*)d_in[0];
    const float* qp      = (const float*)d_in[1];
    const float* refpts  = (const float*)d_in[2];
    const float* src     = (const float*)d_in[3];
    const float* in_w    = (const float*)d_in[4];
    const float* in_b    = (const float*)d_in[5];
    const float* out_w   = (const float*)d_in[6];
    const float* out_b   = (const float*)d_in[7];
    const float* n2g     = (const float*)d_in[8];
    const float* n2b     = (const float*)d_in[9];
    const float* value_w = (const float*)d_in[10];
    const float* value_b = (const float*)d_in[11];
    const float* off_w   = (const float*)d_in[12];
    const float* off_b   = (const float*)d_in[13];
    const float* attw_w  = (const float*)d_in[14];
    const float* attw_b  = (const float*)d_in[15];
    const float* outp_w  = (const float*)d_in[16];
    const float* outp_b  = (const float*)d_in[17];
    const float* n1g     = (const float*)d_in[18];
    const float* n1b     = (const float*)d_in[19];
    const float* lin1_w  = (const float*)d_in[20];
    const float* lin1_b  = (const float*)d_in[21];
    const float* lin2_w  = (const float*)d_in[22];
    const float* lin2_b  = (const float*)d_in[23];
    const float* n3g     = (const float*)d_in[24];
    const float* n3b     = (const float*)d_in[25];

    static float *p_qk, *p_v, *p_att, *p_att2, *p_t1, *p_val, *p_off,
                 *p_attw, *p_samp, *p_ms, *p_t2, *p_f1, *p_f2;
    static bool init = false;
    if (!init) {
        void* p;
        cudaGetSymbolAddress(&p, g_qk);   p_qk   = (float*)p;
        cudaGetSymbolAddress(&p, g_v);    p_v    = (float*)p;
        cudaGetSymbolAddress(&p, g_att);  p_att  = (float*)p;
        cudaGetSymbolAddress(&p, g_att2); p_att2 = (float*)p;
        cudaGetSymbolAddress(&p, g_t1);   p_t1   = (float*)p;
        cudaGetSymbolAddress(&p, g_value);p_val  = (float*)p;
        cudaGetSymbolAddress(&p, g_off);  p_off  = (float*)p;
        cudaGetSymbolAddress(&p, g_attw); p_attw = (float*)p;
        cudaGetSymbolAddress(&p, g_samp); p_samp = (float*)p;
        cudaGetSymbolAddress(&p, g_ms);   p_ms   = (float*)p;
        cudaGetSymbolAddress(&p, g_t2);   p_t2   = (float*)p;
        cudaGetSymbolAddress(&p, g_ffn1); p_f1   = (float*)p;
        cudaGetSymbolAddress(&p, g_ffn2); p_f2   = (float*)p;
        init = true;
    }

    const dim3 gblk(128);

    // 1) q|k = (tgt+qp) @ in_proj_w[0:512]^T
    gemm_tc<<<dim3(512/128, NTOK/128), gblk>>>(tgt, qp, in_w, in_b, p_qk, NTOK, 256, 512, 0);
    // 2) v = tgt @ in_proj_w[512:768]^T
    gemm_tc<<<dim3(256/128, NTOK/128), gblk>>>(tgt, nullptr, in_w + (size_t)512*256, in_b + 512, p_v, NTOK, 256, 256, 0);
    // 3) attention (tensor-core flash)
    attn_tc<<<dim3(LQ/64, BB*HH), dim3(128)>>>(p_qk, p_v, p_att);
    // 4) out_proj
    gemm_tc<<<dim3(256/128, NTOK/128), gblk>>>(p_att, nullptr, out_w, out_b, p_att2, NTOK, 256, 256, 0);
    // 5) t1 = LN(tgt + att2)  [norm2]
    ln_kernel<<<NTOK/8, 256>>>(tgt, p_att2, n2g, n2b, p_t1);
    // 6) value = src @ value_w^T
    gemm_tc<<<dim3(256/128, NV/128), gblk>>>(src, nullptr, value_w, value_b, p_val, NV, 256, 256, 0);
    // 7) off = (t1+qp) @ off_w^T
    gemm_tc<<<dim3(256/128, NTOK/128), gblk>>>(p_t1, qp, off_w, off_b, p_off, NTOK, 256, 256, 0);
    // 8) attw = (t1+qp) @ attw_w^T
    gemm_tc<<<dim3(128/128, NTOK/128), gblk>>>(p_t1, qp, attw_w, attw_b, p_attw, NTOK, 256, 128, 0);
    // 9) softmax over L*P per (token,h)
    softmax16_kernel<<<(NTOK*HH + 255)/256, 256>>>(p_attw);
    // 10) bilinear sampling
    sample_kernel<<<(NTOK*HH)/8, 256>>>(refpts, p_off, p_attw, p_val, p_samp);
    // 11) output projection of deformable attn
    gemm_tc<<<dim3(256/128, NTOK/128), gblk>>>(p_samp, nullptr, outp_w, outp_b, p_ms, NTOK, 256, 256, 0);
    // 12) t2 = LN(t1 + ms)  [norm1]
    ln_kernel<<<NTOK/8, 256>>>(p_t1, p_ms, n1g, n1b, p_t2);
    // 13) ffn1 = relu(t2 @ lin1^T)
    gemm_tc<<<dim3(1024/128, NTOK/128), gblk>>>(p_t2, nullptr, lin1_w, lin1_b, p_f1, NTOK, 256, 1024, 1);
    // 14) ffn2 = ffn1 @ lin2^T
    gemm_tc<<<dim3(256/128, NTOK/128), gblk>>>(p_f1, nullptr, lin2_w, lin2_b, p_f2, NTOK, 1024, 256, 0);
    // 15) out = LN(t2 + ffn2)  [norm3]
    ln_kernel<<<NTOK/8, 256>>>(p_t2, p_f2, n3g, n3b, (float*)d_out);
}

// round 12
// speedup vs baseline: 1.1183x; 1.1183x over previous
#include <cuda_runtime.h>
#include <cuda_bf16.h>
#include <math.h>
#include <stdint.h>

// Problem constants
#define BB   16
#define LQ   1024
#define DD   256
#define HH   8
#define LL   4
#define PP   4
#define DFF  1024
#define LV   5440
#define DH   32
#define NTOK (BB*LQ)        // 16384
#define NV   (BB*LV)        // 87040

__device__ __forceinline__ unsigned f2tf32(float f) {
    unsigned r;
    asm("cvt.rna.tf32.f32 %0, %1;" : "=r"(r) : "f"(f));
    return r;
}
__device__ __forceinline__ void mma_tf32(float* c, const unsigned* a, unsigned b0, unsigned b1) {
    asm volatile(
        "mma.sync.aligned.m16n8k8.row.col.f32.tf32.tf32.f32 "
        "{%0,%1,%2,%3}, {%4,%5,%6,%7}, {%8,%9}, {%0,%1,%2,%3};"
        : "+f"(c[0]), "+f"(c[1]), "+f"(c[2]), "+f"(c[3])
        : "r"(a[0]), "r"(a[1]), "r"(a[2]), "r"(a[3]), "r"(b0), "r"(b1));
}

// ---------------- scratch (device globals; no allocs allowed) ----------------
__device__ float g_qk  [(size_t)NTOK*512];
__device__ float g_v   [(size_t)NTOK*256];
__device__ float g_att [(size_t)NTOK*256];
__device__ float g_att2[(size_t)NTOK*256];
__device__ float g_t1  [(size_t)NTOK*256];
__device__ float g_t1q [(size_t)NTOK*256];
__device__ float g_tq  [(size_t)NTOK*256];
__device__ float g_value[(size_t)NV*256];
__device__ float g_off [(size_t)NTOK*256];
__device__ float g_attw[(size_t)NTOK*128];
__device__ float g_samp[(size_t)NTOK*256];
__device__ float g_ms  [(size_t)NTOK*256];
__device__ float g_t2  [(size_t)NTOK*256];
__device__ float g_ffn1[(size_t)NTOK*1024];
__device__ float g_ffn2[(size_t)NTOK*256];

// ---------------- elementwise add: c = a + b ---------------------------------
__global__ void __launch_bounds__(256) add_kernel(
    const float* __restrict__ a, const float* __restrict__ b, float* __restrict__ c)
{
    const size_t i = ((size_t)blockIdx.x * 256 + threadIdx.x) * 4;
    float4 x = *(const float4*)(a + i);
    float4 y = *(const float4*)(b + i);
    x.x += y.x; x.y += y.y; x.z += y.z; x.w += y.w;
    *(float4*)(c + i) = x;
}

// ---------------- tensor-core GEMM (tf32 mma.sync) — R4 config ---------------
// C[N,M] = A[N,K] @ W[M,K]^T + bias (optional relu)
// 128x128 tile, KC=32, 256 threads = 8 warps (2 row x 4 col), 64x32 per warp.
// smem rows pair-permuted: slot 2t holds k=t, slot 2t+1 holds k=t+4 per 8-group.
#define GSTRIDE 36
__global__ void __launch_bounds__(256, 2) gemm_tc(
    const float* __restrict__ A0,
    const float* __restrict__ W,  const float* __restrict__ bias,
    float* __restrict__ C, int N, int K, int M, int relu)
{
    __shared__ unsigned As[128][GSTRIDE];
    __shared__ unsigned Bs[128][GSTRIDE];

    const int tid  = threadIdx.x;
    const int lane = tid & 31;
    const int wid  = tid >> 5;
    const int wr   = wid & 1;
    const int wc   = wid >> 1;
    const int g    = lane >> 2;
    const int tig  = lane & 3;
    const int r0 = blockIdx.y * 128;
    const int c0 = blockIdx.x * 128;

    float acc[4][4][4];
    #pragma unroll
    for (int mt = 0; mt < 4; mt++)
        #pragma unroll
        for (int nt = 0; nt < 4; nt++)
            #pragma unroll
            for (int c = 0; c < 4; c++) acc[mt][nt][c] = 0.f;

    const int frow = tid >> 1;
    const int fk8  = tid & 1;
    const float* Ap = A0 + (size_t)(r0 + frow) * K;
    const float* Wp = W  + (size_t)(c0 + frow) * K;

    for (int kt = 0; kt < K; kt += 32) {
        __syncthreads();
        #pragma unroll
        for (int it = 0; it < 4; it++) {
            const int ksrc = kt + it * 8 + fk8 * 4;
            float4 a = *(const float4*)(Ap + ksrc);
            float4 b = *(const float4*)(Wp + ksrc);
            const int d = it * 8 + fk8;
            As[frow][d+0] = f2tf32(a.x);
            As[frow][d+2] = f2tf32(a.y);
            As[frow][d+4] = f2tf32(a.z);
            As[frow][d+6] = f2tf32(a.w);
            Bs[frow][d+0] = f2tf32(b.x);
            Bs[frow][d+2] = f2tf32(b.y);
            Bs[frow][d+4] = f2tf32(b.z);
            Bs[frow][d+6] = f2tf32(b.w);
        }
        __syncthreads();

        #pragma unroll
        for (int k8 = 0; k8 < 4; k8++) {
            unsigned af[4][4];
            #pragma unroll
            for (int mt = 0; mt < 4; mt++) {
                const int rowa = wr * 64 + mt * 16 + g;
                uint2 p0 = *(const uint2*)&As[rowa    ][k8 * 8 + 2 * tig];
                uint2 p1 = *(const uint2*)&As[rowa + 8][k8 * 8 + 2 * tig];
                af[mt][0] = p0.x; af[mt][1] = p1.x; af[mt][2] = p0.y; af[mt][3] = p1.y;
            }
            #pragma unroll
            for (int nt = 0; nt < 4; nt++) {
                const int coln = wc * 32 + nt * 8 + g;
                uint2 p = *(const uint2*)&Bs[coln][k8 * 8 + 2 * tig];
                #pragma unroll
                for (int mt = 0; mt < 4; mt++)
                    mma_tf32(acc[mt][nt], af[mt], p.x, p.y);
            }
        }
    }

    #pragma unroll
    for (int nt = 0; nt < 4; nt++) {
        const int col = c0 + wc * 32 + nt * 8 + 2 * tig;
        float2 bi = *(const float2*)(bias + col);
        #pragma unroll
        for (int mt = 0; mt < 4; mt++) {
            const int row = r0 + wr * 64 + mt * 16 + g;
            float2 lo, hi;
            lo.x = acc[mt][nt][0] + bi.x; lo.y = acc[mt][nt][1] + bi.y;
            hi.x = acc[mt][nt][2] + bi.x; hi.y = acc[mt][nt][3] + bi.y;
            if (relu) {
                lo.x = fmaxf(lo.x, 0.f); lo.y = fmaxf(lo.y, 0.f);
                hi.x = fmaxf(hi.x, 0.f); hi.y = fmaxf(hi.y, 0.f);
            }
            *(float2*)(C + (size_t)row * M + col)       = lo;
            *(float2*)(C + (size_t)(row + 8) * M + col) = hi;
        }
    }
}

// ---------------- tensor-core flash attention (tf32) -------------------------
// grid (LQ/64, B*H), 128 threads = 4 warps, 16 queries per warp.
#define KSTR 36
#define VSTR 66
__global__ void __launch_bounds__(128) attn_tc(
    const float* __restrict__ QK, const float* __restrict__ V, float* __restrict__ O)
{
    __shared__ unsigned Ks[64][KSTR];
    __shared__ unsigned Vs[32][VSTR];

    const int bh = blockIdx.y;
    const int b = bh >> 3, h = bh & 7;
    const int q0 = blockIdx.x * 64;
    const int tid = threadIdx.x;
    const int lane = tid & 31;
    const int wid = tid >> 5;
    const int g = lane >> 2;
    const int tig = lane & 3;

    const float scale = 0.17677669529663687f;
    unsigned qf[4][4];
    {
        const size_t qb = ((size_t)b * LQ + q0 + wid * 16) * 512 + h * 32;
        #pragma unroll
        for (int s = 0; s < 4; s++) {
            qf[s][0] = f2tf32(QK[qb + (size_t)g      * 512 + s*8 + tig    ] * scale);
            qf[s][1] = f2tf32(QK[qb + (size_t)(g + 8)* 512 + s*8 + tig    ] * scale);
            qf[s][2] = f2tf32(QK[qb + (size_t)g      * 512 + s*8 + tig + 4] * scale);
            qf[s][3] = f2tf32(QK[qb + (size_t)(g + 8)* 512 + s*8 + tig + 4] * scale);
        }
    }

    float oa[4][4];
    #pragma unroll
    for (int i = 0; i < 4; i++)
        #pragma unroll
        for (int j = 0; j < 4; j++) oa[i][j] = 0.f;
    float m0 = -1e30f, m1 = -1e30f, l0 = 0.f, l1 = 0.f;

    const size_t kbase = ((size_t)b * LQ) * 512 + 256 + h * 32;
    const size_t vbase = ((size_t)b * LQ) * 256 + h * 32;

    for (int kt = 0; kt < LQ; kt += 64) {
        __syncthreads();
        {
            const int key = tid >> 1, kh = (tid & 1) * 16;
            const float* kp = QK + kbase + (size_t)(kt + key) * 512 + kh;
            #pragma unroll
            for (int g2 = 0; g2 < 2; g2++) {
                float4 lo = *(const float4*)(kp + g2 * 8);
                float4 hi = *(const float4*)(kp + g2 * 8 + 4);
                const int d = kh + g2 * 8;
                *(uint2*)&Ks[key][d+0] = make_uint2(f2tf32(lo.x), f2tf32(hi.x));
                *(uint2*)&Ks[key][d+2] = make_uint2(f2tf32(lo.y), f2tf32(hi.y));
                *(uint2*)&Ks[key][d+4] = make_uint2(f2tf32(lo.z), f2tf32(hi.z));
                *(uint2*)&Ks[key][d+6] = make_uint2(f2tf32(lo.w), f2tf32(hi.w));
            }
        }
        {
            const int key = tid >> 1, dh = (tid & 1) * 16;
            const int j = key & 7;
            const int pos = (key >> 3) * 8 + 2 * (j & 3) + (j >> 2);
            const float* vp = V + vbase + (size_t)(kt + key) * 256 + dh;
            #pragma unroll
            for (int i = 0; i < 4; i++) {
                float4 v = *(const float4*)(vp + i * 4);
                Vs[dh + i*4 + 0][pos] = f2tf32(v.x);
                Vs[dh + i*4 + 1][pos] = f2tf32(v.y);
                Vs[dh + i*4 + 2][pos] = f2tf32(v.z);
                Vs[dh + i*4 + 3][pos] = f2tf32(v.w);
            }
        }
        __syncthreads();

        float sa[8][4];
        #pragma unroll
        for (int nt = 0; nt < 8; nt++)
            #pragma unroll
            for (int c = 0; c < 4; c++) sa[nt][c] = 0.f;
        #pragma unroll
        for (int s = 0; s < 4; s++)
            #pragma unroll
            for (int nt = 0; nt < 8; nt++) {
                uint2 p = *(const uint2*)&Ks[nt*8 + g][s*8 + 2*tig];
                mma_tf32(sa[nt], qf[s], p.x, p.y);
            }

        float cm0 = -1e30f, cm1 = -1e30f;
        #pragma unroll
        for (int nt = 0; nt < 8; nt++) {
            cm0 = fmaxf(cm0, fmaxf(sa[nt][0], sa[nt][1]));
            cm1 = fmaxf(cm1, fmaxf(sa[nt][2], sa[nt][3]));
        }
        cm0 = fmaxf(cm0, __shfl_xor_sync(0xffffffffu, cm0, 1));
        cm0 = fmaxf(cm0, __shfl_xor_sync(0xffffffffu, cm0, 2));
        cm1 = fmaxf(cm1, __shfl_xor_sync(0xffffffffu, cm1, 1));
        cm1 = fmaxf(cm1, __shfl_xor_sync(0xffffffffu, cm1, 2));
        const float nm0 = fmaxf(m0, cm0), nm1 = fmaxf(m1, cm1);
        const float r0s = __expf(m0 - nm0), r1s = __expf(m1 - nm1);
        l0 *= r0s; l1 *= r1s;
        #pragma unroll
        for (int d = 0; d < 4; d++) {
            oa[d][0] *= r0s; oa[d][1] *= r0s;
            oa[d][2] *= r1s; oa[d][3] *= r1s;
        }
        float ps0 = 0.f, ps1 = 0.f;
        #pragma unroll
        for (int nt = 0; nt < 8; nt++) {
            sa[nt][0] = __expf(sa[nt][0] - nm0); ps0 += sa[nt][0];
            sa[nt][1] = __expf(sa[nt][1] - nm0); ps0 += sa[nt][1];
            sa[nt][2] = __expf(sa[nt][2] - nm1); ps1 += sa[nt][2];
            sa[nt][3] = __expf(sa[nt][3] - nm1); ps1 += sa[nt][3];
        }
        ps0 += __shfl_xor_sync(0xffffffffu, ps0, 1);
        ps0 += __shfl_xor_sync(0xffffffffu, ps0, 2);
        ps1 += __shfl_xor_sync(0xffffffffu, ps1, 1);
        ps1 += __shfl_xor_sync(0xffffffffu, ps1, 2);
        l0 += ps0; l1 += ps1;
        m0 = nm0; m1 = nm1;

        const int src1 = (lane & ~3) | (tig >> 1);
        const int src2 = src1 + 2;
        #pragma unroll
        for (int nt = 0; nt < 8; nt++) {
            float v0a = __shfl_sync(0xffffffffu, sa[nt][0], src1);
            float v1a = __shfl_sync(0xffffffffu, sa[nt][1], src1);
            float v0b = __shfl_sync(0xffffffffu, sa[nt][0], src2);
            float v1b = __shfl_sync(0xffffffffu, sa[nt][1], src2);
            float w0a = __shfl_sync(0xffffffffu, sa[nt][2], src1);
            float w1a = __shfl_sync(0xffffffffu, sa[nt][3], src1);
            float w0b = __shfl_sync(0xffffffffu, sa[nt][2], src2);
            float w1b = __shfl_sync(0xffffffffu, sa[nt][3], src2);
            unsigned pa[4];
            pa[0] = f2tf32((tig & 1) ? v1a : v0a);
            pa[1] = f2tf32((tig & 1) ? w1a : w0a);
            pa[2] = f2tf32((tig & 1) ? v1b : v0b);
            pa[3] = f2tf32((tig & 1) ? w1b : w0b);
            #pragma unroll
            for (int d = 0; d < 4; d++) {
                uint2 bv = *(const uint2*)&Vs[d*8 + g][nt*8 + 2*tig];
                mma_tf32(oa[d], pa, bv.x, bv.y);
            }
        }
    }

    const float inv0 = 1.f / l0, inv1 = 1.f / l1;
    const size_t orow = ((size_t)b * LQ + q0 + wid * 16 + g) * 256 + h * 32;
    #pragma unroll
    for (int d = 0; d < 4; d++) {
        float2 lo, hi;
        lo.x = oa[d][0] * inv0; lo.y = oa[d][1] * inv0;
        hi.x = oa[d][2] * inv1; hi.y = oa[d][3] * inv1;
        *(float2*)(O + orow + d*8 + 2*tig)            = lo;
        *(float2*)(O + orow + 8*256 + d*8 + 2*tig)    = hi;
    }
}

// ---------------- residual + layernorm: Y = LN(A + Bres) [+ optional Y+qp] ---
__global__ void __launch_bounds__(256) ln_kernel(
    const float* __restrict__ A, const float* __restrict__ Bres,
    const float* __restrict__ g, const float* __restrict__ beta,
    float* __restrict__ Y,
    const float* __restrict__ qp, float* __restrict__ Yq)
{
    const int warp = threadIdx.x >> 5, lane = threadIdx.x & 31;
    const size_t row = (size_t)blockIdx.x * 8 + warp;
    const float* a = A    + row * 256;
    const float* b = Bres + row * 256;
    float v[8];
    #pragma unroll
    for (int i = 0; i < 2; i++) {
        float4 x = *(const float4*)(a + i*128 + lane*4);
        float4 y = *(const float4*)(b + i*128 + lane*4);
        v[i*4+0] = x.x + y.x; v[i*4+1] = x.y + y.y;
        v[i*4+2] = x.z + y.z; v[i*4+3] = x.w + y.w;
    }
    float sum = 0.f, sq = 0.f;
    #pragma unroll
    for (int i = 0; i < 8; i++) { sum += v[i]; sq = fmaf(v[i], v[i], sq); }
    #pragma unroll
    for (int off = 16; off > 0; off >>= 1) {
        sum += __shfl_xor_sync(0xffffffffu, sum, off);
        sq  += __shfl_xor_sync(0xffffffffu, sq,  off);
    }
    const float mean = sum * (1.f/256.f);
    const float var  = sq * (1.f/256.f) - mean * mean;
    const float inv  = rsqrtf(var + 1e-5f);
    #pragma unroll
    for (int i = 0; i < 2; i++) {
        const int col = i*128 + lane*4;
        float4 gg = *(const float4*)(g + col);
        float4 bb = *(const float4*)(beta + col);
        float4 out;
        out.x = (v[i*4+0]-mean)*inv*gg.x + bb.x;
        out.y = (v[i*4+1]-mean)*inv*gg.y + bb.y;
        out.z = (v[i*4+2]-mean)*inv*gg.z + bb.z;
        out.w = (v[i*4+3]-mean)*inv*gg.w + bb.w;
        *(float4*)(Y + row*256 + col) = out;
        if (Yq) {
            float4 qv = *(const float4*)(qp + row*256 + col);
            out.x += qv.x; out.y += qv.y; out.z += qv.z; out.w += qv.w;
            *(float4*)(Yq + row*256 + col) = out;
        }
    }
}

// ---------------- softmax over 16 contiguous values per (token,h) ------------
__global__ void __launch_bounds__(256) softmax16_kernel(float* __restrict__ W)
{
    const int tid = blockIdx.x * 256 + threadIdx.x;
    if (tid >= NTOK * HH) return;
    float* p = W + (size_t)tid * 16;
    float v[16];
    #pragma unroll
    for (int i = 0; i < 4; i++) {
        float4 t = *(const float4*)(p + i*4);
        v[i*4+0]=t.x; v[i*4+1]=t.y; v[i*4+2]=t.z; v[i*4+3]=t.w;
    }
    float mx = v[0];
    #pragma unroll
    for (int i = 1; i < 16; i++) mx = fmaxf(mx, v[i]);
    float s = 0.f;
    #pragma unroll
    for (int i = 0; i < 16; i++) { v[i] = __expf(v[i]-mx); s += v[i]; }
    const float inv = 1.f / s;
    #pragma unroll
    for (int i = 0; i < 4; i++) {
        float4 t;
        t.x=v[i*4+0]*inv; t.y=v[i*4+1]*inv; t.z=v[i*4+2]*inv; t.w=v[i*4+3]*inv;
        *(float4*)(p + i*4) = t;
    }
}

// ---------------- deformable bilinear sampling -------------------------------
__device__ __forceinline__ float fetch_v(const float* __restrict__ value, size_t vb,
                                         int start, int WL2, int HL2, int xi, int yi)
{
    const bool ok = ((unsigned)xi < (unsigned)WL2) & ((unsigned)yi < (unsigned)HL2);
    const int xc = min(max(xi, 0), WL2 - 1);
    const int yc = min(max(yi, 0), HL2 - 1);
    const float val = value[vb + (size_t)(start + yc * WL2 + xc) * 256];
    return ok ? val : 0.f;
}

__global__ void __launch_bounds__(256) sample_kernel(
    const float* __restrict__ ref, const float* __restrict__ off,
    const float* __restrict__ attw, const float* __restrict__ value,
    float* __restrict__ out)
{
    const int wg   = blockIdx.x * 8 + (threadIdx.x >> 5);
    const int lane = threadIdx.x & 31;
    const int h  = wg & 7;
    const int tq = wg >> 3;
    const int b  = tq >> 10;

    const float* refp = ref  + (size_t)tq * (LL*2);
    const float* offp = off  + (size_t)tq * 256 + h * 32;
    const float* awp  = attw + (size_t)tq * 128 + h * 16;
    const size_t vb   = ((size_t)b * LV) * 256 + h * 32 + lane;

    const int wls[4]    = {64, 32, 16, 8};
    const int hls[4]    = {64, 32, 16, 8};
    const int starts[4] = {0, 4096, 5120, 5376};

    float acc = 0.f;
    #pragma unroll
    for (int l = 0; l < 4; l++) {
        const int WL2 = wls[l], HL2 = hls[l], st = starts[l];
        const float rx = refp[l*2], ry = refp[l*2+1];
        #pragma unroll
        for (int p = 0; p < 4; p++) {
            const float ox = offp[(l*4+p)*2];
            const float oy = offp[(l*4+p)*2+1];
            const float aw = awp[l*4+p];
            const float x = fmaf(rx, (float)WL2, ox) - 0.5f;
            const float y = fmaf(ry, (float)HL2, oy) - 0.5f;
            const float xf = floorf(x), yf = floorf(y);
            const float lx = x - xf, ly = y - yf;
            const int x0 = (int)xf, y0 = (int)yf;
            const float v00 = fetch_v(value, vb, st, WL2, HL2, x0,   y0);
            const float v01 = fetch_v(value, vb, st, WL2, HL2, x0+1, y0);
            const float v10 = fetch_v(value, vb, st, WL2, HL2, x0,   y0+1);
            const float v11 = fetch_v(value, vb, st, WL2, HL2, x0+1, y0+1);
            const float top = v00 + lx * (v01 - v00);
            const float bot = v10 + lx * (v11 - v10);
            acc = fmaf(aw, top + ly * (bot - top), acc);
        }
    }
    out[(size_t)tq * 256 + h * 32 + lane] = acc;
}

// ---------------- host orchestration -----------------------------------------
extern "C" void kernel_launch(void* const* d_in, const int* in_sizes, int n_in,
                              void* d_out, int out_size)
{
    const float* tgt     = (const float*)d_in[0];
    const float* qp      = (const float*)d_in[1];
    const float* refpts  = (const float*)d_in[2];
    const float* src     = (const float*)d_in[3];
    const float* in_w    = (const float*)d_in[4];
    const float* in_b    = (const float*)d_in[5];
    const float* out_w   = (const float*)d_in[6];
    const float* out_b   = (const float*)d_in[7];
    const float* n2g     = (const float*)d_in[8];
    const float* n2b     = (const float*)d_in[9];
    const float* value_w = (const float*)d_in[10];
    const float* value_b = (const float*)d_in[11];
    const float* off_w   = (const float*)d_in[12];
    const float* off_b   = (const float*)d_in[13];
    const float* attw_w  = (const float*)d_in[14];
    const float* attw_b  = (const float*)d_in[15];
    const float* outp_w  = (const float*)d_in[16];
    const float* outp_b  = (const float*)d_in[17];
    const float* n1g     = (const float*)d_in[18];
    const float* n1b     = (const float*)d_in[19];
    const float* lin1_w  = (const float*)d_in[20];
    const float* lin1_b  = (const float*)d_in[21];
    const float* lin2_w  = (const float*)d_in[22];
    const float* lin2_b  = (const float*)d_in[23];
    const float* n3g     = (const float*)d_in[24];
    const float* n3b     = (const float*)d_in[25];

    static float *p_qk, *p_v, *p_att, *p_att2, *p_t1, *p_t1q, *p_tq, *p_val,
                 *p_off, *p_attw, *p_samp, *p_ms, *p_t2, *p_f1, *p_f2;
    static bool init = false;
    if (!init) {
        void* p;
        cudaGetSymbolAddress(&p, g_qk);   p_qk   = (float*)p;
        cudaGetSymbolAddress(&p, g_v);    p_v    = (float*)p;
        cudaGetSymbolAddress(&p, g_att);  p_att  = (float*)p;
        cudaGetSymbolAddress(&p, g_att2); p_att2 = (float*)p;
        cudaGetSymbolAddress(&p, g_t1);   p_t1   = (float*)p;
        cudaGetSymbolAddress(&p, g_t1q);  p_t1q  = (float*)p;
        cudaGetSymbolAddress(&p, g_tq);   p_tq   = (float*)p;
        cudaGetSymbolAddress(&p, g_value);p_val  = (float*)p;
        cudaGetSymbolAddress(&p, g_off);  p_off  = (float*)p;
        cudaGetSymbolAddress(&p, g_attw); p_attw = (float*)p;
        cudaGetSymbolAddress(&p, g_samp); p_samp = (float*)p;
        cudaGetSymbolAddress(&p, g_ms);   p_ms   = (float*)p;
        cudaGetSymbolAddress(&p, g_t2);   p_t2   = (float*)p;
        cudaGetSymbolAddress(&p, g_ffn1); p_f1   = (float*)p;
        cudaGetSymbolAddress(&p, g_ffn2); p_f2   = (float*)p;
        init = true;
    }

    const dim3 gblk(256);

    // 0) tq = tgt + qp
    add_kernel<<<(NTOK*256/4)/256, 256>>>(tgt, qp, p_tq);
    // 1) q|k = tq @ in_proj_w[0:512]^T
    gemm_tc<<<dim3(512/128, NTOK/128), gblk>>>(p_tq, in_w, in_b, p_qk, NTOK, 256, 512, 0);
    // 2) v = tgt @ in_proj_w[512:768]^T
    gemm_tc<<<dim3(256/128, NTOK/128), gblk>>>(tgt, in_w + (size_t)512*256, in_b + 512, p_v, NTOK, 256, 256, 0);
    // 3) attention (tensor-core flash)
    attn_tc<<<dim3(LQ/64, BB*HH), dim3(128)>>>(p_qk, p_v, p_att);
    // 4) out_proj
    gemm_tc<<<dim3(256/128, NTOK/128), gblk>>>(p_att, out_w, out_b, p_att2, NTOK, 256, 256, 0);
    // 5) t1 = LN(tgt + att2), t1q = t1 + qp   [norm2]
    ln_kernel<<<NTOK/8, 256>>>(tgt, p_att2, n2g, n2b, p_t1, qp, p_t1q);
    // 6) value = src @ value_w^T
    gemm_tc<<<dim3(256/128, NV/128), gblk>>>(src, value_w, value_b, p_val, NV, 256, 256, 0);
    // 7) off = t1q @ off_w^T
    gemm_tc<<<dim3(256/128, NTOK/128), gblk>>>(p_t1q, off_w, off_b, p_off, NTOK, 256, 256, 0);
    // 8) attw = t1q @ attw_w^T
    gemm_tc<<<dim3(128/128, NTOK/128), gblk>>>(p_t1q, attw_w, attw_b, p_attw, NTOK, 256, 128, 0);
    // 9) softmax over L*P per (token,h)
    softmax16_kernel<<<(NTOK*HH + 255)/256, 256>>>(p_attw);
    // 10) bilinear sampling
    sample_kernel<<<(NTOK*HH)/8, 256>>>(refpts, p_off, p_attw, p_val, p_samp);
    // 11) output projection of deformable attn
    gemm_tc<<<dim3(256/128, NTOK/128), gblk>>>(p_samp, outp_w, outp_b, p_ms, NTOK, 256, 256, 0);
    // 12) t2 = LN(t1 + ms)  [norm1]
    ln_kernel<<<NTOK/8, 256>>>(p_t1, p_ms, n1g, n1b, p_t2, nullptr, nullptr);
    // 13) ffn1 = relu(t2 @ lin1^T)
    gemm_tc<<<dim3(1024/128, NTOK/128), gblk>>>(p_t2, lin1_w, lin1_b, p_f1, NTOK, 256, 1024, 1);
    // 14) ffn2 = ffn1 @ lin2^T
    gemm_tc<<<dim3(256/128, NTOK/128), gblk>>>(p_f1, lin2_w, lin2_b, p_f2, NTOK, 1024, 256, 0);
    // 15) out = LN(t2 + ffn2)  [norm3]
    ln_kernel<<<NTOK/8, 256>>>(p_t2, p_f2, n3g, n3b, (float*)d_out, nullptr, nullptr);
}

// round 15
// speedup vs baseline: 1.2196x; 1.0906x over previous
#include <cuda_runtime.h>
#include <cuda_bf16.h>
#include <math.h>
#include <stdint.h>

// Problem constants
#define BB   16
#define LQ   1024
#define DD   256
#define HH   8
#define LL   4
#define PP   4
#define DFF  1024
#define LV   5440
#define DH   32
#define NTOK (BB*LQ)        // 16384
#define NV   (BB*LV)        // 87040

__device__ __forceinline__ unsigned f2tf32(float f) {
    unsigned r;
    asm("cvt.rna.tf32.f32 %0, %1;" : "=r"(r) : "f"(f));
    return r;
}
__device__ __forceinline__ void mma_tf32(float* c, const unsigned* a, unsigned b0, unsigned b1) {
    asm volatile(
        "mma.sync.aligned.m16n8k8.row.col.f32.tf32.tf32.f32 "
        "{%0,%1,%2,%3}, {%4,%5,%6,%7}, {%8,%9}, {%0,%1,%2,%3};"
        : "+f"(c[0]), "+f"(c[1]), "+f"(c[2]), "+f"(c[3])
        : "r"(a[0]), "r"(a[1]), "r"(a[2]), "r"(a[3]), "r"(b0), "r"(b1));
}

// ---------------- scratch (device globals; no allocs allowed) ----------------
__device__ float g_qk  [(size_t)NTOK*512];
__device__ float g_v   [(size_t)NTOK*256];
__device__ float g_att [(size_t)NTOK*256];
__device__ float g_att2[(size_t)NTOK*256];
__device__ float g_t1  [(size_t)NTOK*256];
__device__ float g_t1q [(size_t)NTOK*256];
__device__ float g_tq  [(size_t)NTOK*256];
__device__ float g_value[(size_t)NV*256];
__device__ float g_off [(size_t)NTOK*256];
__device__ float g_attw[(size_t)NTOK*128];
__device__ float g_samp[(size_t)NTOK*256];
__device__ float g_ms  [(size_t)NTOK*256];
__device__ float g_t2  [(size_t)NTOK*256];
__device__ float g_ffn1[(size_t)NTOK*1024];
__device__ float g_ffn2[(size_t)NTOK*256];

// ---------------- elementwise add: c = a + b ---------------------------------
__global__ void __launch_bounds__(256) add_kernel(
    const float* __restrict__ a, const float* __restrict__ b, float* __restrict__ c)
{
    const size_t i = ((size_t)blockIdx.x * 256 + threadIdx.x) * 4;
    float4 x = *(const float4*)(a + i);
    float4 y = *(const float4*)(b + i);
    x.x += y.x; x.y += y.y; x.z += y.z; x.w += y.w;
    *(float4*)(c + i) = x;
}

// ---------------- tensor-core GEMM (tf32 mma.sync) — R4 config ---------------
#define GSTRIDE 36
__global__ void __launch_bounds__(256, 2) gemm_tc(
    const float* __restrict__ A0,
    const float* __restrict__ W,  const float* __restrict__ bias,
    float* __restrict__ C, int N, int K, int M, int relu)
{
    __shared__ unsigned As[128][GSTRIDE];
    __shared__ unsigned Bs[128][GSTRIDE];

    const int tid  = threadIdx.x;
    const int lane = tid & 31;
    const int wid  = tid >> 5;
    const int wr   = wid & 1;
    const int wc   = wid >> 1;
    const int g    = lane >> 2;
    const int tig  = lane & 3;
    const int r0 = blockIdx.y * 128;
    const int c0 = blockIdx.x * 128;

    float acc[4][4][4];
    #pragma unroll
    for (int mt = 0; mt < 4; mt++)
        #pragma unroll
        for (int nt = 0; nt < 4; nt++)
            #pragma unroll
            for (int c = 0; c < 4; c++) acc[mt][nt][c] = 0.f;

    const int frow = tid >> 1;
    const int fk8  = tid & 1;
    const float* Ap = A0 + (size_t)(r0 + frow) * K;
    const float* Wp = W  + (size_t)(c0 + frow) * K;

    for (int kt = 0; kt < K; kt += 32) {
        __syncthreads();
        #pragma unroll
        for (int it = 0; it < 4; it++) {
            const int ksrc = kt + it * 8 + fk8 * 4;
            float4 a = *(const float4*)(Ap + ksrc);
            float4 b = *(const float4*)(Wp + ksrc);
            const int d = it * 8 + fk8;
            As[frow][d+0] = f2tf32(a.x);
            As[frow][d+2] = f2tf32(a.y);
            As[frow][d+4] = f2tf32(a.z);
            As[frow][d+6] = f2tf32(a.w);
            Bs[frow][d+0] = f2tf32(b.x);
            Bs[frow][d+2] = f2tf32(b.y);
            Bs[frow][d+4] = f2tf32(b.z);
            Bs[frow][d+6] = f2tf32(b.w);
        }
        __syncthreads();

        #pragma unroll
        for (int k8 = 0; k8 < 4; k8++) {
            unsigned af[4][4];
            #pragma unroll
            for (int mt = 0; mt < 4; mt++) {
                const int rowa = wr * 64 + mt * 16 + g;
                uint2 p0 = *(const uint2*)&As[rowa    ][k8 * 8 + 2 * tig];
                uint2 p1 = *(const uint2*)&As[rowa + 8][k8 * 8 + 2 * tig];
                af[mt][0] = p0.x; af[mt][1] = p1.x; af[mt][2] = p0.y; af[mt][3] = p1.y;
            }
            #pragma unroll
            for (int nt = 0; nt < 4; nt++) {
                const int coln = wc * 32 + nt * 8 + g;
                uint2 p = *(const uint2*)&Bs[coln][k8 * 8 + 2 * tig];
                #pragma unroll
                for (int mt = 0; mt < 4; mt++)
                    mma_tf32(acc[mt][nt], af[mt], p.x, p.y);
            }
        }
    }

    #pragma unroll
    for (int nt = 0; nt < 4; nt++) {
        const int col = c0 + wc * 32 + nt * 8 + 2 * tig;
        float2 bi = *(const float2*)(bias + col);
        #pragma unroll
        for (int mt = 0; mt < 4; mt++) {
            const int row = r0 + wr * 64 + mt * 16 + g;
            float2 lo, hi;
            lo.x = acc[mt][nt][0] + bi.x; lo.y = acc[mt][nt][1] + bi.y;
            hi.x = acc[mt][nt][2] + bi.x; hi.y = acc[mt][nt][3] + bi.y;
            if (relu) {
                lo.x = fmaxf(lo.x, 0.f); lo.y = fmaxf(lo.y, 0.f);
                hi.x = fmaxf(hi.x, 0.f); hi.y = fmaxf(hi.y, 0.f);
            }
            *(float2*)(C + (size_t)row * M + col)       = lo;
            *(float2*)(C + (size_t)(row + 8) * M + col) = hi;
        }
    }
}

// ---------------- tensor-core flash attention (tf32, 2 M-tiles/warp) ---------
// grid (LQ/128, B*H), 128 threads = 4 warps, 32 queries per warp (2 m16 tiles).
// Each Ks/Vs B-fragment load feeds 2 MMAs -> LDS/MMA = 0.5.
#define KSTR 36
#define VSTR 66
__global__ void __launch_bounds__(128) attn_tc(
    const float* __restrict__ QK, const float* __restrict__ V, float* __restrict__ O)
{
    __shared__ unsigned Ks[64][KSTR];
    __shared__ unsigned Vs[32][VSTR];

    const int bh = blockIdx.y;
    const int b = bh >> 3, h = bh & 7;
    const int q0 = blockIdx.x * 128;
    const int tid = threadIdx.x;
    const int lane = tid & 31;
    const int wid = tid >> 5;
    const int g = lane >> 2;
    const int tig = lane & 3;

    const float scale = 0.17677669529663687f;
    unsigned qf[2][4][4];
    #pragma unroll
    for (int m = 0; m < 2; m++) {
        const size_t qb = ((size_t)b * LQ + q0 + wid * 32 + m * 16) * 512 + h * 32;
        #pragma unroll
        for (int s = 0; s < 4; s++) {
            qf[m][s][0] = f2tf32(QK[qb + (size_t)g      * 512 + s*8 + tig    ] * scale);
            qf[m][s][1] = f2tf32(QK[qb + (size_t)(g + 8)* 512 + s*8 + tig    ] * scale);
            qf[m][s][2] = f2tf32(QK[qb + (size_t)g      * 512 + s*8 + tig + 4] * scale);
            qf[m][s][3] = f2tf32(QK[qb + (size_t)(g + 8)* 512 + s*8 + tig + 4] * scale);
        }
    }

    float oa[2][4][4];
    #pragma unroll
    for (int m = 0; m < 2; m++)
        #pragma unroll
        for (int i = 0; i < 4; i++)
            #pragma unroll
            for (int j = 0; j < 4; j++) oa[m][i][j] = 0.f;
    float mm[2][2], ll[2][2];
    #pragma unroll
    for (int m = 0; m < 2; m++) { mm[m][0] = -1e30f; mm[m][1] = -1e30f; ll[m][0] = 0.f; ll[m][1] = 0.f; }

    const size_t kbase = ((size_t)b * LQ) * 512 + 256 + h * 32;
    const size_t vbase = ((size_t)b * LQ) * 256 + h * 32;

    for (int kt = 0; kt < LQ; kt += 64) {
        __syncthreads();
        // fill K tile [64 keys x 32 k], pair-permuted
        {
            const int key = tid >> 1, kh = (tid & 1) * 16;
            const float* kp = QK + kbase + (size_t)(kt + key) * 512 + kh;
            #pragma unroll
            for (int g2 = 0; g2 < 2; g2++) {
                float4 lo = *(const float4*)(kp + g2 * 8);
                float4 hi = *(const float4*)(kp + g2 * 8 + 4);
                const int d = kh + g2 * 8;
                *(uint2*)&Ks[key][d+0] = make_uint2(f2tf32(lo.x), f2tf32(hi.x));
                *(uint2*)&Ks[key][d+2] = make_uint2(f2tf32(lo.y), f2tf32(hi.y));
                *(uint2*)&Ks[key][d+4] = make_uint2(f2tf32(lo.z), f2tf32(hi.z));
                *(uint2*)&Ks[key][d+6] = make_uint2(f2tf32(lo.w), f2tf32(hi.w));
            }
        }
        // fill V tile transposed: Vs[d][perm(key)]
        {
            const int key = tid >> 1, dh = (tid & 1) * 16;
            const int j = key & 7;
            const int pos = (key >> 3) * 8 + 2 * (j & 3) + (j >> 2);
            const float* vp = V + vbase + (size_t)(kt + key) * 256 + dh;
            #pragma unroll
            for (int i = 0; i < 4; i++) {
                float4 v = *(const float4*)(vp + i * 4);
                Vs[dh + i*4 + 0][pos] = f2tf32(v.x);
                Vs[dh + i*4 + 1][pos] = f2tf32(v.y);
                Vs[dh + i*4 + 2][pos] = f2tf32(v.z);
                Vs[dh + i*4 + 3][pos] = f2tf32(v.w);
            }
        }
        __syncthreads();

        // S = Q K^T : one B-fragment feeds both m-tiles
        float sa[2][8][4];
        #pragma unroll
        for (int m = 0; m < 2; m++)
            #pragma unroll
            for (int nt = 0; nt < 8; nt++)
                #pragma unroll
                for (int c = 0; c < 4; c++) sa[m][nt][c] = 0.f;
        #pragma unroll
        for (int s = 0; s < 4; s++)
            #pragma unroll
            for (int nt = 0; nt < 8; nt++) {
                uint2 p = *(const uint2*)&Ks[nt*8 + g][s*8 + 2*tig];
                mma_tf32(sa[0][nt], qf[0][s], p.x, p.y);
                mma_tf32(sa[1][nt], qf[1][s], p.x, p.y);
            }

        // online softmax per m-tile
        #pragma unroll
        for (int m = 0; m < 2; m++) {
            float cm0 = -1e30f, cm1 = -1e30f;
            #pragma unroll
            for (int nt = 0; nt < 8; nt++) {
                cm0 = fmaxf(cm0, fmaxf(sa[m][nt][0], sa[m][nt][1]));
                cm1 = fmaxf(cm1, fmaxf(sa[m][nt][2], sa[m][nt][3]));
            }
            cm0 = fmaxf(cm0, __shfl_xor_sync(0xffffffffu, cm0, 1));
            cm0 = fmaxf(cm0, __shfl_xor_sync(0xffffffffu, cm0, 2));
            cm1 = fmaxf(cm1, __shfl_xor_sync(0xffffffffu, cm1, 1));
            cm1 = fmaxf(cm1, __shfl_xor_sync(0xffffffffu, cm1, 2));
            const float nm0 = fmaxf(mm[m][0], cm0), nm1 = fmaxf(mm[m][1], cm1);
            const float r0s = __expf(mm[m][0] - nm0), r1s = __expf(mm[m][1] - nm1);
            ll[m][0] *= r0s; ll[m][1] *= r1s;
            #pragma unroll
            for (int d = 0; d < 4; d++) {
                oa[m][d][0] *= r0s; oa[m][d][1] *= r0s;
                oa[m][d][2] *= r1s; oa[m][d][3] *= r1s;
            }
            float ps0 = 0.f, ps1 = 0.f;
            #pragma unroll
            for (int nt = 0; nt < 8; nt++) {
                sa[m][nt][0] = __expf(sa[m][nt][0] - nm0); ps0 += sa[m][nt][0];
                sa[m][nt][1] = __expf(sa[m][nt][1] - nm0); ps0 += sa[m][nt][1];
                sa[m][nt][2] = __expf(sa[m][nt][2] - nm1); ps1 += sa[m][nt][2];
                sa[m][nt][3] = __expf(sa[m][nt][3] - nm1); ps1 += sa[m][nt][3];
            }
            ps0 += __shfl_xor_sync(0xffffffffu, ps0, 1);
            ps0 += __shfl_xor_sync(0xffffffffu, ps0, 2);
            ps1 += __shfl_xor_sync(0xffffffffu, ps1, 1);
            ps1 += __shfl_xor_sync(0xffffffffu, ps1, 2);
            ll[m][0] += ps0; ll[m][1] += ps1;
            mm[m][0] = nm0; mm[m][1] = nm1;
        }

        // P -> A-layout via shfl; Vs fragments loaded once per (nt,d), reused by both m
        const int src1 = (lane & ~3) | (tig >> 1);
        const int src2 = src1 + 2;
        #pragma unroll
        for (int nt = 0; nt < 8; nt++) {
            uint2 bv[4];
            #pragma unroll
            for (int d = 0; d < 4; d++)
                bv[d] = *(const uint2*)&Vs[d*8 + g][nt*8 + 2*tig];
            #pragma unroll
            for (int m = 0; m < 2; m++) {
                float v0a = __shfl_sync(0xffffffffu, sa[m][nt][0], src1);
                float v1a = __shfl_sync(0xffffffffu, sa[m][nt][1], src1);
                float v0b = __shfl_sync(0xffffffffu, sa[m][nt][0], src2);
                float v1b = __shfl_sync(0xffffffffu, sa[m][nt][1], src2);
                float w0a = __shfl_sync(0xffffffffu, sa[m][nt][2], src1);
                float w1a = __shfl_sync(0xffffffffu, sa[m][nt][3], src1);
                float w0b = __shfl_sync(0xffffffffu, sa[m][nt][2], src2);
                float w1b = __shfl_sync(0xffffffffu, sa[m][nt][3], src2);
                unsigned pa[4];
                pa[0] = f2tf32((tig & 1) ? v1a : v0a);
                pa[1] = f2tf32((tig & 1) ? w1a : w0a);
                pa[2] = f2tf32((tig & 1) ? v1b : v0b);
                pa[3] = f2tf32((tig & 1) ? w1b : w0b);
                #pragma unroll
                for (int d = 0; d < 4; d++)
                    mma_tf32(oa[m][d], pa, bv[d].x, bv[d].y);
            }
        }
    }

    #pragma unroll
    for (int m = 0; m < 2; m++) {
        const float inv0 = 1.f / ll[m][0], inv1 = 1.f / ll[m][1];
        const size_t orow = ((size_t)b * LQ + q0 + wid * 32 + m * 16 + g) * 256 + h * 32;
        #pragma unroll
        for (int d = 0; d < 4; d++) {
            float2 lo, hi;
            lo.x = oa[m][d][0] * inv0; lo.y = oa[m][d][1] * inv0;
            hi.x = oa[m][d][2] * inv1; hi.y = oa[m][d][3] * inv1;
            *(float2*)(O + orow + d*8 + 2*tig)         = lo;
            *(float2*)(O + orow + 8*256 + d*8 + 2*tig) = hi;
        }
    }
}

// ---------------- residual + layernorm: Y = LN(A + Bres) [+ optional Y+qp] ---
__global__ void __launch_bounds__(256) ln_kernel(
    const float* __restrict__ A, const float* __restrict__ Bres,
    const float* __restrict__ g, const float* __restrict__ beta,
    float* __restrict__ Y,
    const float* __restrict__ qp, float* __restrict__ Yq)
{
    const int warp = threadIdx.x >> 5, lane = threadIdx.x & 31;
    const size_t row = (size_t)blockIdx.x * 8 + warp;
    const float* a = A    + row * 256;
    const float* b = Bres + row * 256;
    float v[8];
    #pragma unroll
    for (int i = 0; i < 2; i++) {
        float4 x = *(const float4*)(a + i*128 + lane*4);
        float4 y = *(const float4*)(b + i*128 + lane*4);
        v[i*4+0] = x.x + y.x; v[i*4+1] = x.y + y.y;
        v[i*4+2] = x.z + y.z; v[i*4+3] = x.w + y.w;
    }
    float sum = 0.f, sq = 0.f;
    #pragma unroll
    for (int i = 0; i < 8; i++) { sum += v[i]; sq = fmaf(v[i], v[i], sq); }
    #pragma unroll
    for (int off = 16; off > 0; off >>= 1) {
        sum += __shfl_xor_sync(0xffffffffu, sum, off);
        sq  += __shfl_xor_sync(0xffffffffu, sq,  off);
    }
    const float mean = sum * (1.f/256.f);
    const float var  = sq * (1.f/256.f) - mean * mean;
    const float inv  = rsqrtf(var + 1e-5f);
    #pragma unroll
    for (int i = 0; i < 2; i++) {
        const int col = i*128 + lane*4;
        float4 gg = *(const float4*)(g + col);
        float4 bb = *(const float4*)(beta + col);
        float4 out;
        out.x = (v[i*4+0]-mean)*inv*gg.x + bb.x;
        out.y = (v[i*4+1]-mean)*inv*gg.y + bb.y;
        out.z = (v[i*4+2]-mean)*inv*gg.z + bb.z;
        out.w = (v[i*4+3]-mean)*inv*gg.w + bb.w;
        *(float4*)(Y + row*256 + col) = out;
        if (Yq) {
            float4 qv = *(const float4*)(qp + row*256 + col);
            out.x += qv.x; out.y += qv.y; out.z += qv.z; out.w += qv.w;
            *(float4*)(Yq + row*256 + col) = out;
        }
    }
}

// ---------------- softmax over 16 contiguous values per (token,h) ------------
__global__ void __launch_bounds__(256) softmax16_kernel(float* __restrict__ W)
{
    const int tid = blockIdx.x * 256 + threadIdx.x;
    if (tid >= NTOK * HH) return;
    float* p = W + (size_t)tid * 16;
    float v[16];
    #pragma unroll
    for (int i = 0; i < 4; i++) {
        float4 t = *(const float4*)(p + i*4);
        v[i*4+0]=t.x; v[i*4+1]=t.y; v[i*4+2]=t.z; v[i*4+3]=t.w;
    }
    float mx = v[0];
    #pragma unroll
    for (int i = 1; i < 16; i++) mx = fmaxf(mx, v[i]);
    float s = 0.f;
    #pragma unroll
    for (int i = 0; i < 16; i++) { v[i] = __expf(v[i]-mx); s += v[i]; }
    const float inv = 1.f / s;
    #pragma unroll
    for (int i = 0; i < 4; i++) {
        float4 t;
        t.x=v[i*4+0]*inv; t.y=v[i*4+1]*inv; t.z=v[i*4+2]*inv; t.w=v[i*4+3]*inv;
        *(float4*)(p + i*4) = t;
    }
}

// ---------------- deformable bilinear sampling -------------------------------
__device__ __forceinline__ float fetch_v(const float* __restrict__ value, size_t vb,
                                         int start, int WL2, int HL2, int xi, int yi)
{
    const bool ok = ((unsigned)xi < (unsigned)WL2) & ((unsigned)yi < (unsigned)HL2);
    const int xc = min(max(xi, 0), WL2 - 1);
    const int yc = min(max(yi, 0), HL2 - 1);
    const float val = value[vb + (size_t)(start + yc * WL2 + xc) * 256];
    return ok ? val : 0.f;
}

__global__ void __launch_bounds__(256) sample_kernel(
    const float* __restrict__ ref, const float* __restrict__ off,
    const float* __restrict__ attw, const float* __restrict__ value,
    float* __restrict__ out)
{
    const int wg   = blockIdx.x * 8 + (threadIdx.x >> 5);
    const int lane = threadIdx.x & 31;
    const int h  = wg & 7;
    const int tq = wg >> 3;
    const int b  = tq >> 10;

    const float* refp = ref  + (size_t)tq * (LL*2);
    const float* offp = off  + (size_t)tq * 256 + h * 32;
    const float* awp  = attw + (size_t)tq * 128 + h * 16;
    const size_t vb   = ((size_t)b * LV) * 256 + h * 32 + lane;

    const int wls[4]    = {64, 32, 16, 8};
    const int hls[4]    = {64, 32, 16, 8};
    const int starts[4] = {0, 4096, 5120, 5376};

    float acc = 0.f;
    #pragma unroll
    for (int l = 0; l < 4; l++) {
        const int WL2 = wls[l], HL2 = hls[l], st = starts[l];
        const float rx = refp[l*2], ry = refp[l*2+1];
        #pragma unroll
        for (int p = 0; p < 4; p++) {
            const float ox = offp[(l*4+p)*2];
            const float oy = offp[(l*4+p)*2+1];
            const float aw = awp[l*4+p];
            const float x = fmaf(rx, (float)WL2, ox) - 0.5f;
            const float y = fmaf(ry, (float)HL2, oy) - 0.5f;
            const float xf = floorf(x), yf = floorf(y);
            const float lx = x - xf, ly = y - yf;
            const int x0 = (int)xf, y0 = (int)yf;
            const float v00 = fetch_v(value, vb, st, WL2, HL2, x0,   y0);
            const float v01 = fetch_v(value, vb, st, WL2, HL2, x0+1, y0);
            const float v10 = fetch_v(value, vb, st, WL2, HL2, x0,   y0+1);
            const float v11 = fetch_v(value, vb, st, WL2, HL2, x0+1, y0+1);
            const float top = v00 + lx * (v01 - v00);
            const float bot = v10 + lx * (v11 - v10);
            acc = fmaf(aw, top + ly * (bot - top), acc);
        }
    }
    out[(size_t)tq * 256 + h * 32 + lane] = acc;
}

// ---------------- host orchestration -----------------------------------------
extern "C" void kernel_launch(void* const* d_in, const int* in_sizes, int n_in,
                              void* d_out, int out_size)
{
    const float* tgt     = (const float*)d_in[0];
    const float* qp      = (const float*)d_in[1];
    const float* refpts  = (const float*)d_in[2];
    const float* src     = (const float*)d_in[3];
    const float* in_w    = (const float*)d_in[4];
    const float* in_b    = (const float*)d_in[5];
    const float* out_w   = (const float*)d_in[6];
    const float* out_b   = (const float*)d_in[7];
    const float* n2g     = (const float*)d_in[8];
    const float* n2b     = (const float*)d_in[9];
    const float* value_w = (const float*)d_in[10];
    const float* value_b = (const float*)d_in[11];
    const float* off_w   = (const float*)d_in[12];
    const float* off_b   = (const float*)d_in[13];
    const float* attw_w  = (const float*)d_in[14];
    const float* attw_b  = (const float*)d_in[15];
    const float* outp_w  = (const float*)d_in[16];
    const float* outp_b  = (const float*)d_in[17];
    const float* n1g     = (const float*)d_in[18];
    const float* n1b     = (const float*)d_in[19];
    const float* lin1_w  = (const float*)d_in[20];
    const float* lin1_b  = (const float*)d_in[21];
    const float* lin2_w  = (const float*)d_in[22];
    const float* lin2_b  = (const float*)d_in[23];
    const float* n3g     = (const float*)d_in[24];
    const float* n3b     = (const float*)d_in[25];

    static float *p_qk, *p_v, *p_att, *p_att2, *p_t1, *p_t1q, *p_tq, *p_val,
                 *p_off, *p_attw, *p_samp, *p_ms, *p_t2, *p_f1, *p_f2;
    static bool init = false;
    if (!init) {
        void* p;
        cudaGetSymbolAddress(&p, g_qk);   p_qk   = (float*)p;
        cudaGetSymbolAddress(&p, g_v);    p_v    = (float*)p;
        cudaGetSymbolAddress(&p, g_att);  p_att  = (float*)p;
        cudaGetSymbolAddress(&p, g_att2); p_att2 = (float*)p;
        cudaGetSymbolAddress(&p, g_t1);   p_t1   = (float*)p;
        cudaGetSymbolAddress(&p, g_t1q);  p_t1q  = (float*)p;
        cudaGetSymbolAddress(&p, g_tq);   p_tq   = (float*)p;
        cudaGetSymbolAddress(&p, g_value);p_val  = (float*)p;
        cudaGetSymbolAddress(&p, g_off);  p_off  = (float*)p;
        cudaGetSymbolAddress(&p, g_attw); p_attw = (float*)p;
        cudaGetSymbolAddress(&p, g_samp); p_samp = (float*)p;
        cudaGetSymbolAddress(&p, g_ms);   p_ms   = (float*)p;
        cudaGetSymbolAddress(&p, g_t2);   p_t2   = (float*)p;
        cudaGetSymbolAddress(&p, g_ffn1); p_f1   = (float*)p;
        cudaGetSymbolAddress(&p, g_ffn2); p_f2   = (float*)p;
        init = true;
    }

    const dim3 gblk(256);

    // 0) tq = tgt + qp
    add_kernel<<<(NTOK*256/4)/256, 256>>>(tgt, qp, p_tq);
    // 1) q|k = tq @ in_proj_w[0:512]^T
    gemm_tc<<<dim3(512/128, NTOK/128), gblk>>>(p_tq, in_w, in_b, p_qk, NTOK, 256, 512, 0);
    // 2) v = tgt @ in_proj_w[512:768]^T
    gemm_tc<<<dim3(256/128, NTOK/128), gblk>>>(tgt, in_w + (size_t)512*256, in_b + 512, p_v, NTOK, 256, 256, 0);
    // 3) attention (tensor-core flash, 128 queries/CTA)
    attn_tc<<<dim3(LQ/128, BB*HH), dim3(128)>>>(p_qk, p_v, p_att);
    // 4) out_proj
    gemm_tc<<<dim3(256/128, NTOK/128), gblk>>>(p_att, out_w, out_b, p_att2, NTOK, 256, 256, 0);
    // 5) t1 = LN(tgt + att2), t1q = t1 + qp   [norm2]
    ln_kernel<<<NTOK/8, 256>>>(tgt, p_att2, n2g, n2b, p_t1, qp, p_t1q);
    // 6) value = src @ value_w^T
    gemm_tc<<<dim3(256/128, NV/128), gblk>>>(src, value_w, value_b, p_val, NV, 256, 256, 0);
    // 7) off = t1q @ off_w^T
    gemm_tc<<<dim3(256/128, NTOK/128), gblk>>>(p_t1q, off_w, off_b, p_off, NTOK, 256, 256, 0);
    // 8) attw = t1q @ attw_w^T
    gemm_tc<<<dim3(128/128, NTOK/128), gblk>>>(p_t1q, attw_w, attw_b, p_attw, NTOK, 256, 128, 0);
    // 9) softmax over L*P per (token,h)
    softmax16_kernel<<<(NTOK*HH + 255)/256, 256>>>(p_attw);
    // 10) bilinear sampling
    sample_kernel<<<(NTOK*HH)/8, 256>>>(refpts, p_off, p_attw, p_val, p_samp);
    // 11) output projection of deformable attn
    gemm_tc<<<dim3(256/128, NTOK/128), gblk>>>(p_samp, outp_w, outp_b, p_ms, NTOK, 256, 256, 0);
    // 12) t2 = LN(t1 + ms)  [norm1]
    ln_kernel<<<NTOK/8, 256>>>(p_t1, p_ms, n1g, n1b, p_t2, nullptr, nullptr);
    // 13) ffn1 = relu(t2 @ lin1^T)
    gemm_tc<<<dim3(1024/128, NTOK/128), gblk>>>(p_t2, lin1_w, lin1_b, p_f1, NTOK, 256, 1024, 1);
    // 14) ffn2 = ffn1 @ lin2^T
    gemm_tc<<<dim3(256/128, NTOK/128), gblk>>>(p_f1, lin2_w, lin2_b, p_f2, NTOK, 1024, 256, 0);
    // 15) out = LN(t2 + ffn2)  [norm3]
    ln_kernel<<<NTOK/8, 256>>>(p_t2, p_f2, n3g, n3b, (float*)d_out, nullptr, nullptr);
}